// round 11
// baseline (speedup 1.0000x reference)
#include <cuda_runtime.h>

#define B_SZ 8192
#define K_SZ 25
#define L_SZ 25
#define NCELL 512
#define BN_EPS 1e-5f

typedef unsigned long long u64;

__device__ float g_sum[L_SZ];
__device__ float g_sumsq[L_SZ];
__device__ unsigned g_minu[L_SZ];
__device__ unsigned g_maxu[L_SZ];
__device__ float g_xT[L_SZ * B_SZ];            // raw x, transposed [L][B]
__device__ float g_lpA[L_SZ], g_lpC[L_SZ];     // u = fma(x, A, C)
__device__ float g_lpXmin[L_SZ], g_lpH[L_SZ];  // xn-grid origin/step
__device__ float2 g_table[K_SZ * L_SZ * NCELL];// {alpha*f0, alpha*df} per cell

// ---------- packed f32x2 helpers ----------
__device__ __forceinline__ u64 pack2(float a, float b) {
    u64 r;
    asm("mov.b64 %0, {%1, %2};" : "=l"(r) : "r"(__float_as_uint(a)), "r"(__float_as_uint(b)));
    return r;
}
__device__ __forceinline__ u64 dup2(float a) { return pack2(a, a); }
__device__ __forceinline__ float2 unpack2(u64 v) {
    unsigned lo, hi;
    asm("mov.b64 {%0, %1}, %2;" : "=r"(lo), "=r"(hi) : "l"(v));
    return make_float2(__uint_as_float(lo), __uint_as_float(hi));
}
__device__ __forceinline__ u64 ffma2(u64 a, u64 b, u64 c) {
    u64 d;
    asm("fma.rn.f32x2 %0, %1, %2, %3;" : "=l"(d) : "l"(a), "l"(b), "l"(c));
    return d;
}
__device__ __forceinline__ u64 relu2(u64 v) {
    float2 f = unpack2(v);
    return pack2(fmaxf(f.x, 0.f), fmaxf(f.y, 0.f));
}

// order-preserving float->uint map (for atomicMin/Max)
__device__ __forceinline__ unsigned fmap(float f) {
    int i = __float_as_int(f);
    return (i < 0) ? ~(unsigned)i : ((unsigned)i | 0x80000000u);
}
__device__ __forceinline__ float funmap(unsigned u) {
    int i = (u & 0x80000000u) ? (int)(u & 0x7FFFFFFFu) : ~(int)u;
    return __int_as_float(i);
}

// ---------- kernel 1: stats(sum,sq,min,max) + transpose + out=beta ----------
__global__ void __launch_bounds__(128) prologue_kernel(
    const float* __restrict__ x,
    const float* __restrict__ beta,
    float* __restrict__ out)
{
    __shared__ float t[64][27];
    __shared__ float ps[4][32], pq[4][32], pmn[4][32], pmx[4][32];
    __shared__ float sbeta[L_SZ];
    const int tid  = threadIdx.x;
    const int base = blockIdx.x * 64;

    if (tid < L_SZ) sbeta[tid] = beta[tid];
    __syncthreads();

    #pragma unroll
    for (int i = tid; i < 64 * L_SZ; i += 128) {
        int r = i / L_SZ, c = i - r * L_SZ;
        t[r][c] = x[base * L_SZ + i];
        out[base * L_SZ + i] = sbeta[c];
    }
    __syncthreads();

    {
        const int c = tid & 31, g = tid >> 5;
        float s = 0.f, q = 0.f, mn = 3.0e38f, mx = -3.0e38f;
        if (c < L_SZ) {
            #pragma unroll
            for (int r = g; r < 64; r += 4) {
                float v = t[r][c];
                s += v;
                q = fmaf(v, v, q);
                mn = fminf(mn, v);
                mx = fmaxf(mx, v);
            }
        }
        ps[g][c] = s; pq[g][c] = q; pmn[g][c] = mn; pmx[g][c] = mx;
    }
    __syncthreads();
    if (tid < L_SZ) {
        float S = ps[0][tid] + ps[1][tid] + ps[2][tid] + ps[3][tid];
        float Q = pq[0][tid] + pq[1][tid] + pq[2][tid] + pq[3][tid];
        float MN = fminf(fminf(pmn[0][tid], pmn[1][tid]), fminf(pmn[2][tid], pmn[3][tid]));
        float MX = fmaxf(fmaxf(pmx[0][tid], pmx[1][tid]), fmaxf(pmx[2][tid], pmx[3][tid]));
        atomicAdd(&g_sum[tid], S);
        atomicAdd(&g_sumsq[tid], Q);
        atomicMin(&g_minu[tid], fmap(MN));
        atomicMax(&g_maxu[tid], fmap(MX));
    }

    #pragma unroll
    for (int i = tid; i < L_SZ * 64; i += 128) {
        int l = i >> 6, r = i & 63;
        g_xT[l * B_SZ + base + r] = t[r][l];
    }
}

// ---------- kernel 2: per-l grid parameters ----------
__global__ void lparam_kernel(const float* __restrict__ gamma,
                              const float* __restrict__ bn_bias) {
    int l = threadIdx.x;
    if (l >= L_SZ) return;
    float mean = g_sum[l] * (1.f / (float)B_SZ);
    float var  = g_sumsq[l] * (1.f / (float)B_SZ) - mean * mean;
    float sc   = gamma[l] * rsqrtf(var + BN_EPS);
    float sh   = bn_bias[l] - mean * sc;
    float xmin = funmap(g_minu[l]);
    float xmax = funmap(g_maxu[l]);
    float a1 = fmaf(sc, xmin, sh), a2 = fmaf(sc, xmax, sh);
    float xnmin = fminf(a1, a2), xnmax = fmaxf(a1, a2);
    float range = xnmax - xnmin;
    float h     = range / (float)NCELL;
    float inv_h = (float)NCELL / range;
    g_lpXmin[l] = xnmin;
    g_lpH[l]    = h;
    g_lpA[l]    = sc * inv_h;
    g_lpC[l]    = (sh - xnmin) * inv_h;
}

// ---------- kernel 3: tabulate each net on its grid ----------
__global__ void __launch_bounds__(128) build_kernel(
    const float* __restrict__ W1, const float* __restrict__ b1,
    const float* __restrict__ W2, const float* __restrict__ b2,
    const float* __restrict__ W3, const float* __restrict__ b3,
    const float* __restrict__ W4, const float* __restrict__ b4,
    const float* __restrict__ alpha)
{
    __shared__ __align__(16) u64 sw1[8], sb1[8], sw2[64], sb2[8], sw3[48], sb3[6], sw4[6];
    __shared__ u64 sb4;
    __shared__ float nodes[NCELL + 2];

    const int l = blockIdx.x, k = blockIdx.y, tid = threadIdx.x;
    const int nb = k * L_SZ + l;

    if (tid < 8)  sw1[tid] = dup2(W1[nb * 8 + tid]);
    if (tid < 8)  sb1[tid] = dup2(b1[nb * 8 + tid]);
    if (tid < 64) sw2[tid] = dup2(W2[nb * 64 + tid]);
    if (tid < 8)  sb2[tid] = dup2(b2[nb * 8 + tid]);
    if (tid < 48) sw3[tid] = dup2(W3[nb * 48 + tid]);
    if (tid < 6)  sb3[tid] = dup2(b3[nb * 6 + tid]);
    if (tid < 6)  sw4[tid] = dup2(W4[nb * 6 + tid]);
    if (tid == 0) sb4 = dup2(b4[nb]);
    __syncthreads();

    const float xnmin = g_lpXmin[l];
    const float h     = g_lpH[l];

    // evaluate node pairs (2i, 2i+1), packed f32x2
    for (int i = tid; i < NCELL / 2 + 1; i += 128) {
        float x0 = fmaf((float)(2 * i), h, xnmin);
        u64 xn = pack2(x0, x0 + h);

        u64 h1[8];
        #pragma unroll
        for (int j = 0; j < 8; ++j) h1[j] = relu2(ffma2(xn, sw1[j], sb1[j]));
        u64 h2[8];
        #pragma unroll
        for (int j = 0; j < 8; ++j) {
            u64 a = sb2[j];
            #pragma unroll
            for (int q = 0; q < 8; ++q) a = ffma2(h1[q], sw2[j * 8 + q], a);
            h2[j] = relu2(a);
        }
        u64 h3[6];
        #pragma unroll
        for (int j = 0; j < 6; ++j) {
            u64 a = sb3[j];
            #pragma unroll
            for (int q = 0; q < 8; ++q) a = ffma2(h2[q], sw3[j * 8 + q], a);
            h3[j] = relu2(a);
        }
        u64 f = sb4;
        #pragma unroll
        for (int j = 0; j < 6; ++j) f = ffma2(h3[j], sw4[j], f);

        float2 fv = unpack2(f);
        int n0 = 2 * i;
        if (n0 <= NCELL)     nodes[n0] = fv.x;
        if (n0 + 1 <= NCELL) nodes[n0 + 1] = fv.y;
    }
    __syncthreads();

    const float al = alpha[l * K_SZ + k];
    float2* dst = g_table + nb * NCELL;
    for (int i = tid; i < NCELL; i += 128) {
        float f0 = nodes[i], f1 = nodes[i + 1];
        dst[i] = make_float2(al * f0, al * (f1 - f0));
    }
}

// ---------- kernel 4: table-based evaluation, 2 l's per block ----------
__global__ void __launch_bounds__(128) eval_kernel(float* __restrict__ out) {
    __shared__ __align__(16) float2 tb[2][NCELL];   // double-buffered 4KB tables
    __shared__ float sA[L_SZ], sC[L_SZ];

    const int tid = threadIdx.x;
    const int k   = blockIdx.y;
    const int z   = blockIdx.z;
    const int lstart = z * 2;
    const int nl     = (lstart + 2 <= L_SZ) ? 2 : 1;
    const int b0  = blockIdx.x * 2048 + tid * 16;

    if (tid < L_SZ) { sA[tid] = g_lpA[tid]; sC[tid] = g_lpC[tid]; }

    // fill buffer 0 (4KB = 256 float4 -> 2 per thread)
    {
        const float4* src = (const float4*)(g_table + (k * L_SZ + lstart) * NCELL);
        float4* d4 = (float4*)tb[0];
        d4[tid]       = src[tid];
        d4[tid + 128] = src[tid + 128];
    }
    __syncthreads();

    float acc[16];
    #pragma unroll
    for (int i = 0; i < 16; ++i) acc[i] = 0.f;

    #pragma unroll 1
    for (int li = 0; li < nl; ++li) {
        if (li + 1 < nl) {   // prefetch next table into other buffer
            const float4* src = (const float4*)(g_table + (k * L_SZ + lstart + li + 1) * NCELL);
            float4* d4 = (float4*)tb[(li + 1) & 1];
            d4[tid]       = src[tid];
            d4[tid + 128] = src[tid + 128];
        }
        const float2* T = tb[li & 1];
        const float A = sA[lstart + li], C = sC[lstart + li];
        const float4* xp = (const float4*)(g_xT + (lstart + li) * B_SZ + b0);
        #pragma unroll
        for (int q = 0; q < 4; ++q) {
            float4 xv = xp[q];
            float xs[4] = {xv.x, xv.y, xv.z, xv.w};
            #pragma unroll
            for (int c = 0; c < 4; ++c) {
                float u = fmaf(xs[c], A, C);
                int idx = __float2int_rd(u);
                idx = min(max(idx, 0), NCELL - 1);
                float frac = u - (float)idx;
                float2 td = T[idx];
                acc[q * 4 + c] += fmaf(frac, td.y, td.x);
            }
        }
        __syncthreads();
    }

    #pragma unroll
    for (int i = 0; i < 16; ++i)
        atomicAdd(out + (b0 + i) * K_SZ + k, acc[i]);
}

extern "C" void kernel_launch(void* const* d_in, const int* in_sizes, int n_in,
                              void* d_out, int out_size) {
    const float* x      = (const float*)d_in[0];
    const float* gamma  = (const float*)d_in[1];
    const float* bnb    = (const float*)d_in[2];
    const float* W1     = (const float*)d_in[3];
    const float* b1     = (const float*)d_in[4];
    const float* W2     = (const float*)d_in[5];
    const float* b2     = (const float*)d_in[6];
    const float* W3     = (const float*)d_in[7];
    const float* b3     = (const float*)d_in[8];
    const float* W4     = (const float*)d_in[9];
    const float* b4     = (const float*)d_in[10];
    const float* alpha  = (const float*)d_in[11];
    const float* beta   = (const float*)d_in[12];
    float* out = (float*)d_out;

    void *p_sum, *p_sq, *p_mn, *p_mx;
    cudaGetSymbolAddress(&p_sum, g_sum);
    cudaGetSymbolAddress(&p_sq,  g_sumsq);
    cudaGetSymbolAddress(&p_mn,  g_minu);
    cudaGetSymbolAddress(&p_mx,  g_maxu);
    cudaMemsetAsync(p_sum, 0,    L_SZ * sizeof(float));
    cudaMemsetAsync(p_sq,  0,    L_SZ * sizeof(float));
    cudaMemsetAsync(p_mn,  0xFF, L_SZ * sizeof(unsigned));
    cudaMemsetAsync(p_mx,  0x00, L_SZ * sizeof(unsigned));

    prologue_kernel<<<B_SZ / 64, 128>>>(x, beta, out);
    lparam_kernel<<<1, 32>>>(gamma, bnb);
    build_kernel<<<dim3(L_SZ, K_SZ), 128>>>(W1, b1, W2, b2, W3, b3, W4, b4, alpha);
    eval_kernel<<<dim3(B_SZ / 2048, K_SZ, (L_SZ + 1) / 2), 128>>>(out);
}

// round 12
// speedup vs baseline: 1.1722x; 1.1722x over previous
#include <cuda_runtime.h>

#define B_SZ 8192
#define K_SZ 25
#define L_SZ 25
#define NCELL 256
#define KCHUNK 5
#define BN_EPS 1e-5f

typedef unsigned long long u64;

__device__ float g_sum[L_SZ];
__device__ float g_sumsq[L_SZ];
__device__ unsigned g_minu[L_SZ];
__device__ unsigned g_maxu[L_SZ];
__device__ float g_xT[L_SZ * B_SZ];            // raw x, transposed [L][B]
__device__ float g_lpA[L_SZ], g_lpC[L_SZ];     // u = fma(x, A, C)
__device__ float g_lpXmin[L_SZ], g_lpH[L_SZ];  // xn-grid origin/step
__device__ float2 g_table[L_SZ * NCELL * K_SZ];// [l][cell][k] = {alpha*f0, alpha*df}

// ---------- packed f32x2 helpers ----------
__device__ __forceinline__ u64 pack2(float a, float b) {
    u64 r;
    asm("mov.b64 %0, {%1, %2};" : "=l"(r) : "r"(__float_as_uint(a)), "r"(__float_as_uint(b)));
    return r;
}
__device__ __forceinline__ u64 dup2(float a) { return pack2(a, a); }
__device__ __forceinline__ float2 unpack2(u64 v) {
    unsigned lo, hi;
    asm("mov.b64 {%0, %1}, %2;" : "=r"(lo), "=r"(hi) : "l"(v));
    return make_float2(__uint_as_float(lo), __uint_as_float(hi));
}
__device__ __forceinline__ u64 ffma2(u64 a, u64 b, u64 c) {
    u64 d;
    asm("fma.rn.f32x2 %0, %1, %2, %3;" : "=l"(d) : "l"(a), "l"(b), "l"(c));
    return d;
}
__device__ __forceinline__ u64 relu2(u64 v) {
    float2 f = unpack2(v);
    return pack2(fmaxf(f.x, 0.f), fmaxf(f.y, 0.f));
}

// order-preserving float->uint map (for atomicMin/Max)
__device__ __forceinline__ unsigned fmap(float f) {
    int i = __float_as_int(f);
    return (i < 0) ? ~(unsigned)i : ((unsigned)i | 0x80000000u);
}
__device__ __forceinline__ float funmap(unsigned u) {
    int i = (u & 0x80000000u) ? (int)(u & 0x7FFFFFFFu) : ~(int)u;
    return __int_as_float(i);
}

// ---------- kernel 1: stats(sum,sq,min,max) + transpose ----------
__global__ void __launch_bounds__(128) prologue_kernel(const float* __restrict__ x)
{
    __shared__ float t[64][27];
    __shared__ float ps[4][32], pq[4][32], pmn[4][32], pmx[4][32];
    const int tid  = threadIdx.x;
    const int base = blockIdx.x * 64;

    #pragma unroll
    for (int i = tid; i < 64 * L_SZ; i += 128) {
        int r = i / L_SZ, c = i - r * L_SZ;
        t[r][c] = x[base * L_SZ + i];
    }
    __syncthreads();

    {
        const int c = tid & 31, g = tid >> 5;
        float s = 0.f, q = 0.f, mn = 3.0e38f, mx = -3.0e38f;
        if (c < L_SZ) {
            #pragma unroll
            for (int r = g; r < 64; r += 4) {
                float v = t[r][c];
                s += v;
                q = fmaf(v, v, q);
                mn = fminf(mn, v);
                mx = fmaxf(mx, v);
            }
        }
        ps[g][c] = s; pq[g][c] = q; pmn[g][c] = mn; pmx[g][c] = mx;
    }
    __syncthreads();
    if (tid < L_SZ) {
        float S = ps[0][tid] + ps[1][tid] + ps[2][tid] + ps[3][tid];
        float Q = pq[0][tid] + pq[1][tid] + pq[2][tid] + pq[3][tid];
        float MN = fminf(fminf(pmn[0][tid], pmn[1][tid]), fminf(pmn[2][tid], pmn[3][tid]));
        float MX = fmaxf(fmaxf(pmx[0][tid], pmx[1][tid]), fmaxf(pmx[2][tid], pmx[3][tid]));
        atomicAdd(&g_sum[tid], S);
        atomicAdd(&g_sumsq[tid], Q);
        atomicMin(&g_minu[tid], fmap(MN));
        atomicMax(&g_maxu[tid], fmap(MX));
    }

    #pragma unroll
    for (int i = tid; i < L_SZ * 64; i += 128) {
        int l = i >> 6, r = i & 63;
        g_xT[l * B_SZ + base + r] = t[r][l];
    }
}

// ---------- kernel 2: per-l grid parameters ----------
__global__ void lparam_kernel(const float* __restrict__ gamma,
                              const float* __restrict__ bn_bias) {
    int l = threadIdx.x;
    if (l >= L_SZ) return;
    float mean = g_sum[l] * (1.f / (float)B_SZ);
    float var  = g_sumsq[l] * (1.f / (float)B_SZ) - mean * mean;
    float sc   = gamma[l] * rsqrtf(var + BN_EPS);
    float sh   = bn_bias[l] - mean * sc;
    float xmin = funmap(g_minu[l]);
    float xmax = funmap(g_maxu[l]);
    float a1 = fmaf(sc, xmin, sh), a2 = fmaf(sc, xmax, sh);
    float xnmin = fminf(a1, a2), xnmax = fmaxf(a1, a2);
    float range = xnmax - xnmin;
    float h     = range / (float)NCELL;
    float inv_h = (float)NCELL / range;
    g_lpXmin[l] = xnmin;
    g_lpH[l]    = h;
    g_lpA[l]    = sc * inv_h;
    g_lpC[l]    = (sh - xnmin) * inv_h;
}

// ---------- kernel 3: tabulate each net, layout [l][cell][k] ----------
__global__ void __launch_bounds__(128) build_kernel(
    const float* __restrict__ W1, const float* __restrict__ b1,
    const float* __restrict__ W2, const float* __restrict__ b2,
    const float* __restrict__ W3, const float* __restrict__ b3,
    const float* __restrict__ W4, const float* __restrict__ b4,
    const float* __restrict__ alpha)
{
    __shared__ __align__(16) u64 sw1[8], sb1[8], sw2[64], sb2[8], sw3[48], sb3[6], sw4[6];
    __shared__ u64 sb4;
    __shared__ float nodes[NCELL + 2];

    const int l = blockIdx.x, k = blockIdx.y, tid = threadIdx.x;
    const int nb = k * L_SZ + l;

    if (tid < 8)  sw1[tid] = dup2(W1[nb * 8 + tid]);
    if (tid < 8)  sb1[tid] = dup2(b1[nb * 8 + tid]);
    if (tid < 64) sw2[tid] = dup2(W2[nb * 64 + tid]);
    if (tid < 8)  sb2[tid] = dup2(b2[nb * 8 + tid]);
    if (tid < 48) sw3[tid] = dup2(W3[nb * 48 + tid]);
    if (tid < 6)  sb3[tid] = dup2(b3[nb * 6 + tid]);
    if (tid < 6)  sw4[tid] = dup2(W4[nb * 6 + tid]);
    if (tid == 0) sb4 = dup2(b4[nb]);
    __syncthreads();

    const float xnmin = g_lpXmin[l];
    const float h     = g_lpH[l];

    // evaluate node pairs (2i, 2i+1), packed f32x2
    for (int i = tid; i < NCELL / 2 + 1; i += 128) {
        float x0 = fmaf((float)(2 * i), h, xnmin);
        u64 xn = pack2(x0, x0 + h);

        u64 h1[8];
        #pragma unroll
        for (int j = 0; j < 8; ++j) h1[j] = relu2(ffma2(xn, sw1[j], sb1[j]));
        u64 h2[8];
        #pragma unroll
        for (int j = 0; j < 8; ++j) {
            u64 a = sb2[j];
            #pragma unroll
            for (int q = 0; q < 8; ++q) a = ffma2(h1[q], sw2[j * 8 + q], a);
            h2[j] = relu2(a);
        }
        u64 h3[6];
        #pragma unroll
        for (int j = 0; j < 6; ++j) {
            u64 a = sb3[j];
            #pragma unroll
            for (int q = 0; q < 8; ++q) a = ffma2(h2[q], sw3[j * 8 + q], a);
            h3[j] = relu2(a);
        }
        u64 f = sb4;
        #pragma unroll
        for (int j = 0; j < 6; ++j) f = ffma2(h3[j], sw4[j], f);

        float2 fv = unpack2(f);
        int n0 = 2 * i;
        if (n0 <= NCELL)     nodes[n0] = fv.x;
        if (n0 + 1 <= NCELL) nodes[n0 + 1] = fv.y;
    }
    __syncthreads();

    const float al = alpha[l * K_SZ + k];
    // transposed layout: [l][cell][k]
    for (int i = tid; i < NCELL; i += 128) {
        float f0 = nodes[i], f1 = nodes[i + 1];
        g_table[(l * NCELL + i) * K_SZ + k] = make_float2(al * f0, al * (f1 - f0));
    }
}

// ---------- kernel 4: gather-contiguous eval, no smem, no atomics ----------
__global__ void __launch_bounds__(128) eval_kernel(
    const float* __restrict__ beta, float* __restrict__ out)
{
    __shared__ float sA[L_SZ], sC[L_SZ];
    const int tid = threadIdx.x;
    const int b   = blockIdx.x * 128 + tid;      // sample
    const int kb  = blockIdx.y * KCHUNK;         // k-chunk base

    if (tid < L_SZ) { sA[tid] = g_lpA[tid]; sC[tid] = g_lpC[tid]; }
    __syncthreads();

    float acc[KCHUNK];
    #pragma unroll
    for (int j = 0; j < KCHUNK; ++j) acc[j] = beta[kb + j];

    #pragma unroll 5
    for (int l = 0; l < L_SZ; ++l) {
        float xv = g_xT[l * B_SZ + b];           // coalesced across threads
        float u  = fmaf(xv, sA[l], sC[l]);
        int idx  = __float2int_rd(u);
        idx = min(max(idx, 0), NCELL - 1);
        float frac = u - (float)idx;
        const float2* T = g_table + (l * NCELL + idx) * K_SZ + kb;
        #pragma unroll
        for (int j = 0; j < KCHUNK; ++j) {
            float2 td = T[j];                    // contiguous 40B per thread
            acc[j] = fmaf(frac, td.y, acc[j] + td.x) - 0.f;
        }
    }

    #pragma unroll
    for (int j = 0; j < KCHUNK; ++j)
        out[b * K_SZ + kb + j] = acc[j];
}

extern "C" void kernel_launch(void* const* d_in, const int* in_sizes, int n_in,
                              void* d_out, int out_size) {
    const float* x      = (const float*)d_in[0];
    const float* gamma  = (const float*)d_in[1];
    const float* bnb    = (const float*)d_in[2];
    const float* W1     = (const float*)d_in[3];
    const float* b1     = (const float*)d_in[4];
    const float* W2     = (const float*)d_in[5];
    const float* b2     = (const float*)d_in[6];
    const float* W3     = (const float*)d_in[7];
    const float* b3     = (const float*)d_in[8];
    const float* W4     = (const float*)d_in[9];
    const float* b4     = (const float*)d_in[10];
    const float* alpha  = (const float*)d_in[11];
    const float* beta   = (const float*)d_in[12];
    float* out = (float*)d_out;

    void *p_sum, *p_sq, *p_mn, *p_mx;
    cudaGetSymbolAddress(&p_sum, g_sum);
    cudaGetSymbolAddress(&p_sq,  g_sumsq);
    cudaGetSymbolAddress(&p_mn,  g_minu);
    cudaGetSymbolAddress(&p_mx,  g_maxu);
    cudaMemsetAsync(p_sum, 0,    L_SZ * sizeof(float));
    cudaMemsetAsync(p_sq,  0,    L_SZ * sizeof(float));
    cudaMemsetAsync(p_mn,  0xFF, L_SZ * sizeof(unsigned));
    cudaMemsetAsync(p_mx,  0x00, L_SZ * sizeof(unsigned));

    prologue_kernel<<<B_SZ / 64, 128>>>(x);
    lparam_kernel<<<1, 32>>>(gamma, bnb);
    build_kernel<<<dim3(L_SZ, K_SZ), 128>>>(W1, b1, W2, b2, W3, b3, W4, b4, alpha);
    eval_kernel<<<dim3(B_SZ / 128, K_SZ / KCHUNK), 128>>>(beta, out);
}

// round 13
// speedup vs baseline: 1.3193x; 1.1255x over previous
#include <cuda_runtime.h>

#define B_SZ 8192
#define K_SZ 25
#define L_SZ 25
#define NCELL 256
#define KCHUNK 5
#define LSPLIT 5
#define BN_EPS 1e-5f

typedef unsigned long long u64;

__device__ float g_sum[L_SZ];
__device__ float g_sumsq[L_SZ];
__device__ unsigned g_minu[L_SZ];
__device__ unsigned g_maxu[L_SZ];
__device__ float g_xT[L_SZ * B_SZ];            // raw x, transposed [L][B]
__device__ float g_lpA[L_SZ], g_lpC[L_SZ];     // u = fma(x, A, C)
__device__ float g_lpXmin[L_SZ], g_lpH[L_SZ];  // xn-grid origin/step
__device__ float2 g_table[L_SZ * NCELL * K_SZ];// [l][cell][k] = {alpha*f0, alpha*df}

// ---------- packed f32x2 helpers ----------
__device__ __forceinline__ u64 pack2(float a, float b) {
    u64 r;
    asm("mov.b64 %0, {%1, %2};" : "=l"(r) : "r"(__float_as_uint(a)), "r"(__float_as_uint(b)));
    return r;
}
__device__ __forceinline__ u64 dup2(float a) { return pack2(a, a); }
__device__ __forceinline__ float2 unpack2(u64 v) {
    unsigned lo, hi;
    asm("mov.b64 {%0, %1}, %2;" : "=r"(lo), "=r"(hi) : "l"(v));
    return make_float2(__uint_as_float(lo), __uint_as_float(hi));
}
__device__ __forceinline__ u64 ffma2(u64 a, u64 b, u64 c) {
    u64 d;
    asm("fma.rn.f32x2 %0, %1, %2, %3;" : "=l"(d) : "l"(a), "l"(b), "l"(c));
    return d;
}
__device__ __forceinline__ u64 relu2(u64 v) {
    float2 f = unpack2(v);
    return pack2(fmaxf(f.x, 0.f), fmaxf(f.y, 0.f));
}

// order-preserving float->uint map (for atomicMin/Max)
__device__ __forceinline__ unsigned fmap(float f) {
    int i = __float_as_int(f);
    return (i < 0) ? ~(unsigned)i : ((unsigned)i | 0x80000000u);
}
__device__ __forceinline__ float funmap(unsigned u) {
    int i = (u & 0x80000000u) ? (int)(u & 0x7FFFFFFFu) : ~(int)u;
    return __int_as_float(i);
}

// ---------- kernel 1: stats(sum,sq,min,max) + transpose + out=beta ----------
__global__ void __launch_bounds__(128) prologue_kernel(
    const float* __restrict__ x,
    const float* __restrict__ beta,
    float* __restrict__ out)
{
    __shared__ float t[64][27];
    __shared__ float ps[4][32], pq[4][32], pmn[4][32], pmx[4][32];
    __shared__ float sbeta[L_SZ];
    const int tid  = threadIdx.x;
    const int base = blockIdx.x * 64;

    if (tid < K_SZ) sbeta[tid] = beta[tid];
    __syncthreads();

    #pragma unroll
    for (int i = tid; i < 64 * L_SZ; i += 128) {
        int r = i / L_SZ, c = i - r * L_SZ;
        t[r][c] = x[base * L_SZ + i];
        out[base * K_SZ + i] = sbeta[c];      // init out with beta[k] (K_SZ==L_SZ)
    }
    __syncthreads();

    {
        const int c = tid & 31, g = tid >> 5;
        float s = 0.f, q = 0.f, mn = 3.0e38f, mx = -3.0e38f;
        if (c < L_SZ) {
            #pragma unroll
            for (int r = g; r < 64; r += 4) {
                float v = t[r][c];
                s += v;
                q = fmaf(v, v, q);
                mn = fminf(mn, v);
                mx = fmaxf(mx, v);
            }
        }
        ps[g][c] = s; pq[g][c] = q; pmn[g][c] = mn; pmx[g][c] = mx;
    }
    __syncthreads();
    if (tid < L_SZ) {
        float S = ps[0][tid] + ps[1][tid] + ps[2][tid] + ps[3][tid];
        float Q = pq[0][tid] + pq[1][tid] + pq[2][tid] + pq[3][tid];
        float MN = fminf(fminf(pmn[0][tid], pmn[1][tid]), fminf(pmn[2][tid], pmn[3][tid]));
        float MX = fmaxf(fmaxf(pmx[0][tid], pmx[1][tid]), fmaxf(pmx[2][tid], pmx[3][tid]));
        atomicAdd(&g_sum[tid], S);
        atomicAdd(&g_sumsq[tid], Q);
        atomicMin(&g_minu[tid], fmap(MN));
        atomicMax(&g_maxu[tid], fmap(MX));
    }

    #pragma unroll
    for (int i = tid; i < L_SZ * 64; i += 128) {
        int l = i >> 6, r = i & 63;
        g_xT[l * B_SZ + base + r] = t[r][l];
    }
}

// ---------- kernel 2: per-l grid parameters ----------
__global__ void lparam_kernel(const float* __restrict__ gamma,
                              const float* __restrict__ bn_bias) {
    int l = threadIdx.x;
    if (l >= L_SZ) return;
    float mean = g_sum[l] * (1.f / (float)B_SZ);
    float var  = g_sumsq[l] * (1.f / (float)B_SZ) - mean * mean;
    float sc   = gamma[l] * rsqrtf(var + BN_EPS);
    float sh   = bn_bias[l] - mean * sc;
    float xmin = funmap(g_minu[l]);
    float xmax = funmap(g_maxu[l]);
    float a1 = fmaf(sc, xmin, sh), a2 = fmaf(sc, xmax, sh);
    float xnmin = fminf(a1, a2), xnmax = fmaxf(a1, a2);
    float range = xnmax - xnmin;
    float h     = range / (float)NCELL;
    float inv_h = (float)NCELL / range;
    g_lpXmin[l] = xnmin;
    g_lpH[l]    = h;
    g_lpA[l]    = sc * inv_h;
    g_lpC[l]    = (sh - xnmin) * inv_h;
}

// ---------- kernel 3: tabulate each net, layout [l][cell][k] ----------
__global__ void __launch_bounds__(128) build_kernel(
    const float* __restrict__ W1, const float* __restrict__ b1,
    const float* __restrict__ W2, const float* __restrict__ b2,
    const float* __restrict__ W3, const float* __restrict__ b3,
    const float* __restrict__ W4, const float* __restrict__ b4,
    const float* __restrict__ alpha)
{
    __shared__ __align__(16) u64 sw1[8], sb1[8], sw2[64], sb2[8], sw3[48], sb3[6], sw4[6];
    __shared__ u64 sb4;
    __shared__ float nodes[NCELL + 2];

    const int l = blockIdx.x, k = blockIdx.y, tid = threadIdx.x;
    const int nb = k * L_SZ + l;

    if (tid < 8)  sw1[tid] = dup2(W1[nb * 8 + tid]);
    if (tid < 8)  sb1[tid] = dup2(b1[nb * 8 + tid]);
    if (tid < 64) sw2[tid] = dup2(W2[nb * 64 + tid]);
    if (tid < 8)  sb2[tid] = dup2(b2[nb * 8 + tid]);
    if (tid < 48) sw3[tid] = dup2(W3[nb * 48 + tid]);
    if (tid < 6)  sb3[tid] = dup2(b3[nb * 6 + tid]);
    if (tid < 6)  sw4[tid] = dup2(W4[nb * 6 + tid]);
    if (tid == 0) sb4 = dup2(b4[nb]);
    __syncthreads();

    const float xnmin = g_lpXmin[l];
    const float h     = g_lpH[l];

    // evaluate node pairs (2i, 2i+1), packed f32x2
    for (int i = tid; i < NCELL / 2 + 1; i += 128) {
        float x0 = fmaf((float)(2 * i), h, xnmin);
        u64 xn = pack2(x0, x0 + h);

        u64 h1[8];
        #pragma unroll
        for (int j = 0; j < 8; ++j) h1[j] = relu2(ffma2(xn, sw1[j], sb1[j]));
        u64 h2[8];
        #pragma unroll
        for (int j = 0; j < 8; ++j) {
            u64 a = sb2[j];
            #pragma unroll
            for (int q = 0; q < 8; ++q) a = ffma2(h1[q], sw2[j * 8 + q], a);
            h2[j] = relu2(a);
        }
        u64 h3[6];
        #pragma unroll
        for (int j = 0; j < 6; ++j) {
            u64 a = sb3[j];
            #pragma unroll
            for (int q = 0; q < 8; ++q) a = ffma2(h2[q], sw3[j * 8 + q], a);
            h3[j] = relu2(a);
        }
        u64 f = sb4;
        #pragma unroll
        for (int j = 0; j < 6; ++j) f = ffma2(h3[j], sw4[j], f);

        float2 fv = unpack2(f);
        int n0 = 2 * i;
        if (n0 <= NCELL)     nodes[n0] = fv.x;
        if (n0 + 1 <= NCELL) nodes[n0 + 1] = fv.y;
    }
    __syncthreads();

    const float al = alpha[l * K_SZ + k];
    // transposed layout: [l][cell][k]
    for (int i = tid; i < NCELL; i += 128) {
        float f0 = nodes[i], f1 = nodes[i + 1];
        g_table[(l * NCELL + i) * K_SZ + k] = make_float2(al * f0, al * (f1 - f0));
    }
}

// ---------- kernel 4: gather-contiguous eval, l-split, atomic combine ----------
__global__ void __launch_bounds__(128) eval_kernel(float* __restrict__ out)
{
    const int tid = threadIdx.x;
    const int b   = blockIdx.x * 128 + tid;      // sample
    const int kb  = blockIdx.y * KCHUNK;         // k-chunk base
    const int lb  = blockIdx.z * LSPLIT;         // l-chunk base

    float acc[KCHUNK];
    #pragma unroll
    for (int j = 0; j < KCHUNK; ++j) acc[j] = 0.f;

    #pragma unroll
    for (int li = 0; li < LSPLIT; ++li) {
        const int l = lb + li;
        float xv = g_xT[l * B_SZ + b];           // coalesced across threads
        float u  = fmaf(xv, g_lpA[l], g_lpC[l]);
        int idx  = __float2int_rd(u);
        idx = min(max(idx, 0), NCELL - 1);
        float frac = u - (float)idx;
        const float2* T = g_table + (l * NCELL + idx) * K_SZ + kb;
        #pragma unroll
        for (int j = 0; j < KCHUNK; ++j) {
            float2 td = T[j];                    // contiguous 40B per thread
            acc[j] += fmaf(frac, td.y, td.x);
        }
    }

    #pragma unroll
    for (int j = 0; j < KCHUNK; ++j)
        atomicAdd(out + b * K_SZ + kb + j, acc[j]);
}

extern "C" void kernel_launch(void* const* d_in, const int* in_sizes, int n_in,
                              void* d_out, int out_size) {
    const float* x      = (const float*)d_in[0];
    const float* gamma  = (const float*)d_in[1];
    const float* bnb    = (const float*)d_in[2];
    const float* W1     = (const float*)d_in[3];
    const float* b1     = (const float*)d_in[4];
    const float* W2     = (const float*)d_in[5];
    const float* b2     = (const float*)d_in[6];
    const float* W3     = (const float*)d_in[7];
    const float* b3     = (const float*)d_in[8];
    const float* W4     = (const float*)d_in[9];
    const float* b4     = (const float*)d_in[10];
    const float* alpha  = (const float*)d_in[11];
    const float* beta   = (const float*)d_in[12];
    float* out = (float*)d_out;

    void *p_sum, *p_sq, *p_mn, *p_mx;
    cudaGetSymbolAddress(&p_sum, g_sum);
    cudaGetSymbolAddress(&p_sq,  g_sumsq);
    cudaGetSymbolAddress(&p_mn,  g_minu);
    cudaGetSymbolAddress(&p_mx,  g_maxu);
    cudaMemsetAsync(p_sum, 0,    L_SZ * sizeof(float));
    cudaMemsetAsync(p_sq,  0,    L_SZ * sizeof(float));
    cudaMemsetAsync(p_mn,  0xFF, L_SZ * sizeof(unsigned));
    cudaMemsetAsync(p_mx,  0x00, L_SZ * sizeof(unsigned));

    prologue_kernel<<<B_SZ / 64, 128>>>(x, beta, out);
    lparam_kernel<<<1, 32>>>(gamma, bnb);
    build_kernel<<<dim3(L_SZ, K_SZ), 128>>>(W1, b1, W2, b2, W3, b3, W4, b4, alpha);
    eval_kernel<<<dim3(B_SZ / 128, K_SZ / KCHUNK, L_SZ / LSPLIT), 128>>>(out);
}

// round 14
// speedup vs baseline: 1.5774x; 1.1957x over previous
#include <cuda_runtime.h>

#define B_SZ 8192
#define K_SZ 25
#define L_SZ 25
#define NCELL 256
#define BN_EPS 1e-5f

typedef unsigned long long u64;

struct Stats {
    float sum[L_SZ];
    float sumsq[L_SZ];
    unsigned mininv[L_SZ];   // max over ~fmap(v)  -> min = funmap(~mininv)
    unsigned maxu[L_SZ];     // max over  fmap(v)
};
__device__ Stats g_st;
__device__ float g_xT[L_SZ * B_SZ];            // raw x, transposed [L][B]
__device__ float g_lpA[L_SZ], g_lpC[L_SZ];     // u = fma(x, A, C)
__device__ float g_lpXmin[L_SZ], g_lpH[L_SZ];  // xn-grid origin/step
__device__ float2 g_table[L_SZ * NCELL * K_SZ];// [l][cell][k] = {alpha*f0, alpha*df}

// ---------- packed f32x2 helpers ----------
__device__ __forceinline__ u64 pack2(float a, float b) {
    u64 r;
    asm("mov.b64 %0, {%1, %2};" : "=l"(r) : "r"(__float_as_uint(a)), "r"(__float_as_uint(b)));
    return r;
}
__device__ __forceinline__ u64 dup2(float a) { return pack2(a, a); }
__device__ __forceinline__ float2 unpack2(u64 v) {
    unsigned lo, hi;
    asm("mov.b64 {%0, %1}, %2;" : "=r"(lo), "=r"(hi) : "l"(v));
    return make_float2(__uint_as_float(lo), __uint_as_float(hi));
}
__device__ __forceinline__ u64 ffma2(u64 a, u64 b, u64 c) {
    u64 d;
    asm("fma.rn.f32x2 %0, %1, %2, %3;" : "=l"(d) : "l"(a), "l"(b), "l"(c));
    return d;
}
__device__ __forceinline__ u64 relu2(u64 v) {
    float2 f = unpack2(v);
    return pack2(fmaxf(f.x, 0.f), fmaxf(f.y, 0.f));
}

// order-preserving float->uint map
__device__ __forceinline__ unsigned fmap(float f) {
    int i = __float_as_int(f);
    return (i < 0) ? ~(unsigned)i : ((unsigned)i | 0x80000000u);
}
__device__ __forceinline__ float funmap(unsigned u) {
    int i = (u & 0x80000000u) ? (int)(u & 0x7FFFFFFFu) : ~(int)u;
    return __int_as_float(i);
}

// ---------- kernel 1: stats(sum,sq,min,max) + transpose ----------
__global__ void __launch_bounds__(128) prologue_kernel(const float* __restrict__ x)
{
    __shared__ float t[64][27];
    __shared__ float ps[4][32], pq[4][32], pmn[4][32], pmx[4][32];
    const int tid  = threadIdx.x;
    const int base = blockIdx.x * 64;

    #pragma unroll
    for (int i = tid; i < 64 * L_SZ; i += 128) {
        int r = i / L_SZ, c = i - r * L_SZ;
        t[r][c] = x[base * L_SZ + i];
    }
    __syncthreads();

    {
        const int c = tid & 31, g = tid >> 5;
        float s = 0.f, q = 0.f, mn = 3.0e38f, mx = -3.0e38f;
        if (c < L_SZ) {
            #pragma unroll
            for (int r = g; r < 64; r += 4) {
                float v = t[r][c];
                s += v;
                q = fmaf(v, v, q);
                mn = fminf(mn, v);
                mx = fmaxf(mx, v);
            }
        }
        ps[g][c] = s; pq[g][c] = q; pmn[g][c] = mn; pmx[g][c] = mx;
    }
    __syncthreads();
    if (tid < L_SZ) {
        float S = ps[0][tid] + ps[1][tid] + ps[2][tid] + ps[3][tid];
        float Q = pq[0][tid] + pq[1][tid] + pq[2][tid] + pq[3][tid];
        float MN = fminf(fminf(pmn[0][tid], pmn[1][tid]), fminf(pmn[2][tid], pmn[3][tid]));
        float MX = fmaxf(fmaxf(pmx[0][tid], pmx[1][tid]), fmaxf(pmx[2][tid], pmx[3][tid]));
        atomicAdd(&g_st.sum[tid], S);
        atomicAdd(&g_st.sumsq[tid], Q);
        atomicMax(&g_st.mininv[tid], ~fmap(MN));
        atomicMax(&g_st.maxu[tid], fmap(MX));
    }

    #pragma unroll
    for (int i = tid; i < L_SZ * 64; i += 128) {
        int l = i >> 6, r = i & 63;
        g_xT[l * B_SZ + base + r] = t[r][l];
    }
}

// ---------- kernel 2: per-l grid parameters ----------
__global__ void lparam_kernel(const float* __restrict__ gamma,
                              const float* __restrict__ bn_bias) {
    int l = threadIdx.x;
    if (l >= L_SZ) return;
    float mean = g_st.sum[l] * (1.f / (float)B_SZ);
    float var  = g_st.sumsq[l] * (1.f / (float)B_SZ) - mean * mean;
    float sc   = gamma[l] * rsqrtf(var + BN_EPS);
    float sh   = bn_bias[l] - mean * sc;
    float xmin = funmap(~g_st.mininv[l]);
    float xmax = funmap(g_st.maxu[l]);
    float a1 = fmaf(sc, xmin, sh), a2 = fmaf(sc, xmax, sh);
    float xnmin = fminf(a1, a2), xnmax = fmaxf(a1, a2);
    float range = xnmax - xnmin;
    float h     = range / (float)NCELL;
    float inv_h = (float)NCELL / range;
    g_lpXmin[l] = xnmin;
    g_lpH[l]    = h;
    g_lpA[l]    = sc * inv_h;
    g_lpC[l]    = (sh - xnmin) * inv_h;
}

// ---------- kernel 3: tabulate each net, layout [l][cell][k] ----------
__global__ void __launch_bounds__(128) build_kernel(
    const float* __restrict__ W1, const float* __restrict__ b1,
    const float* __restrict__ W2, const float* __restrict__ b2,
    const float* __restrict__ W3, const float* __restrict__ b3,
    const float* __restrict__ W4, const float* __restrict__ b4,
    const float* __restrict__ alpha)
{
    __shared__ __align__(16) u64 sw1[8], sb1[8], sw2[64], sb2[8], sw3[48], sb3[6], sw4[6];
    __shared__ u64 sb4;
    __shared__ float nodes[NCELL + 2];

    const int l = blockIdx.x, k = blockIdx.y, tid = threadIdx.x;
    const int nb = k * L_SZ + l;

    if (tid < 8)  sw1[tid] = dup2(W1[nb * 8 + tid]);
    if (tid < 8)  sb1[tid] = dup2(b1[nb * 8 + tid]);
    if (tid < 64) sw2[tid] = dup2(W2[nb * 64 + tid]);
    if (tid < 8)  sb2[tid] = dup2(b2[nb * 8 + tid]);
    if (tid < 48) sw3[tid] = dup2(W3[nb * 48 + tid]);
    if (tid < 6)  sb3[tid] = dup2(b3[nb * 6 + tid]);
    if (tid < 6)  sw4[tid] = dup2(W4[nb * 6 + tid]);
    if (tid == 0) sb4 = dup2(b4[nb]);
    __syncthreads();

    const float xnmin = g_lpXmin[l];
    const float h     = g_lpH[l];

    // evaluate node pairs (2i, 2i+1), packed f32x2
    for (int i = tid; i < NCELL / 2 + 1; i += 128) {
        float x0 = fmaf((float)(2 * i), h, xnmin);
        u64 xn = pack2(x0, x0 + h);

        u64 h1[8];
        #pragma unroll
        for (int j = 0; j < 8; ++j) h1[j] = relu2(ffma2(xn, sw1[j], sb1[j]));
        u64 h2[8];
        #pragma unroll
        for (int j = 0; j < 8; ++j) {
            u64 a = sb2[j];
            #pragma unroll
            for (int q = 0; q < 8; ++q) a = ffma2(h1[q], sw2[j * 8 + q], a);
            h2[j] = relu2(a);
        }
        u64 h3[6];
        #pragma unroll
        for (int j = 0; j < 6; ++j) {
            u64 a = sb3[j];
            #pragma unroll
            for (int q = 0; q < 8; ++q) a = ffma2(h2[q], sw3[j * 8 + q], a);
            h3[j] = relu2(a);
        }
        u64 f = sb4;
        #pragma unroll
        for (int j = 0; j < 6; ++j) f = ffma2(h3[j], sw4[j], f);

        float2 fv = unpack2(f);
        int n0 = 2 * i;
        if (n0 <= NCELL)     nodes[n0] = fv.x;
        if (n0 + 1 <= NCELL) nodes[n0 + 1] = fv.y;
    }
    __syncthreads();

    const float al = alpha[l * K_SZ + k];
    for (int i = tid; i < NCELL; i += 128) {
        float f0 = nodes[i], f1 = nodes[i + 1];
        g_table[(l * NCELL + i) * K_SZ + k] = make_float2(al * f0, al * (f1 - f0));
    }
}

// ---------- kernel 4: warp-per-sample eval, k on lanes, fully coalesced ----------
__global__ void __launch_bounds__(128) eval_kernel(
    const float* __restrict__ beta, float* __restrict__ out)
{
    __shared__ float sA[32], sC[32];
    const int tid  = threadIdx.x;
    const int lane = tid & 31;
    const int warp = tid >> 5;
    if (tid < L_SZ) { sA[tid] = g_lpA[tid]; sC[tid] = g_lpC[tid]; }
    __syncthreads();

    const int b = blockIdx.x * 4 + warp;          // one sample per warp
    float acc = (lane < K_SZ) ? beta[lane] : 0.f;

    #pragma unroll
    for (int l = 0; l < L_SZ; ++l) {
        float xv = g_xT[l * B_SZ + b];            // uniform broadcast load
        float u  = fmaf(xv, sA[l], sC[l]);
        int idx  = __float2int_rd(u);
        idx = min(max(idx, 0), NCELL - 1);
        float frac = u - (float)idx;
        if (lane < K_SZ) {
            float2 td = g_table[(l * NCELL + idx) * K_SZ + lane];  // 200B contiguous/warp
            acc += fmaf(frac, td.y, td.x);
        }
    }

    if (lane < K_SZ) out[b * K_SZ + lane] = acc;
}

extern "C" void kernel_launch(void* const* d_in, const int* in_sizes, int n_in,
                              void* d_out, int out_size) {
    const float* x      = (const float*)d_in[0];
    const float* gamma  = (const float*)d_in[1];
    const float* bnb    = (const float*)d_in[2];
    const float* W1     = (const float*)d_in[3];
    const float* b1     = (const float*)d_in[4];
    const float* W2     = (const float*)d_in[5];
    const float* b2     = (const float*)d_in[6];
    const float* W3     = (const float*)d_in[7];
    const float* b3     = (const float*)d_in[8];
    const float* W4     = (const float*)d_in[9];
    const float* b4     = (const float*)d_in[10];
    const float* alpha  = (const float*)d_in[11];
    const float* beta   = (const float*)d_in[12];
    float* out = (float*)d_out;

    void* p_st = nullptr;
    cudaGetSymbolAddress(&p_st, g_st);
    cudaMemsetAsync(p_st, 0, sizeof(Stats));   // zero = identity for all four reductions

    prologue_kernel<<<B_SZ / 64, 128>>>(x);
    lparam_kernel<<<1, 32>>>(gamma, bnb);
    build_kernel<<<dim3(L_SZ, K_SZ), 128>>>(W1, b1, W2, b2, W3, b3, W4, b4, alpha);
    eval_kernel<<<B_SZ / 4, 128>>>(beta, out);
}

// round 15
// speedup vs baseline: 1.8771x; 1.1900x over previous
#include <cuda_runtime.h>

#define B_SZ 8192
#define K_SZ 25
#define L_SZ 25
#define NCELL 256
#define BN_EPS 1e-5f

typedef unsigned long long u64;

struct Stats {
    float sum[L_SZ];
    float sumsq[L_SZ];
    unsigned mininv[L_SZ];   // max over ~fmap(v)  -> min = funmap(~mininv)
    unsigned maxu[L_SZ];     // max over  fmap(v)
};
__device__ Stats g_st;
__device__ float g_lpA[L_SZ], g_lpC[L_SZ];     // u = fma(x, A, C)
__device__ float g_lpXmin[L_SZ], g_lpH[L_SZ];  // xn-grid origin/step
__device__ float2 g_table[L_SZ * NCELL * K_SZ];// [l][cell][k] = {alpha*f0, alpha*df}

// ---------- packed f32x2 helpers ----------
__device__ __forceinline__ u64 pack2(float a, float b) {
    u64 r;
    asm("mov.b64 %0, {%1, %2};" : "=l"(r) : "r"(__float_as_uint(a)), "r"(__float_as_uint(b)));
    return r;
}
__device__ __forceinline__ u64 dup2(float a) { return pack2(a, a); }
__device__ __forceinline__ float2 unpack2(u64 v) {
    unsigned lo, hi;
    asm("mov.b64 {%0, %1}, %2;" : "=r"(lo), "=r"(hi) : "l"(v));
    return make_float2(__uint_as_float(lo), __uint_as_float(hi));
}
__device__ __forceinline__ u64 ffma2(u64 a, u64 b, u64 c) {
    u64 d;
    asm("fma.rn.f32x2 %0, %1, %2, %3;" : "=l"(d) : "l"(a), "l"(b), "l"(c));
    return d;
}
__device__ __forceinline__ u64 relu2(u64 v) {
    float2 f = unpack2(v);
    return pack2(fmaxf(f.x, 0.f), fmaxf(f.y, 0.f));
}

// order-preserving float->uint map
__device__ __forceinline__ unsigned fmap(float f) {
    int i = __float_as_int(f);
    return (i < 0) ? ~(unsigned)i : ((unsigned)i | 0x80000000u);
}
__device__ __forceinline__ float funmap(unsigned u) {
    int i = (u & 0x80000000u) ? (int)(u & 0x7FFFFFFFu) : ~(int)u;
    return __int_as_float(i);
}

// ---------- kernel 1: stats(sum,sq,min,max) only ----------
__global__ void __launch_bounds__(128) prologue_kernel(const float* __restrict__ x)
{
    __shared__ float t[64][27];
    __shared__ float ps[4][32], pq[4][32], pmn[4][32], pmx[4][32];
    const int tid  = threadIdx.x;
    const int base = blockIdx.x * 64;

    #pragma unroll
    for (int i = tid; i < 64 * L_SZ; i += 128) {
        int r = i / L_SZ, c = i - r * L_SZ;
        t[r][c] = x[base * L_SZ + i];
    }
    __syncthreads();

    {
        const int c = tid & 31, g = tid >> 5;
        float s = 0.f, q = 0.f, mn = 3.0e38f, mx = -3.0e38f;
        if (c < L_SZ) {
            #pragma unroll
            for (int r = g; r < 64; r += 4) {
                float v = t[r][c];
                s += v;
                q = fmaf(v, v, q);
                mn = fminf(mn, v);
                mx = fmaxf(mx, v);
            }
        }
        ps[g][c] = s; pq[g][c] = q; pmn[g][c] = mn; pmx[g][c] = mx;
    }
    __syncthreads();
    if (tid < L_SZ) {
        float S = ps[0][tid] + ps[1][tid] + ps[2][tid] + ps[3][tid];
        float Q = pq[0][tid] + pq[1][tid] + pq[2][tid] + pq[3][tid];
        float MN = fminf(fminf(pmn[0][tid], pmn[1][tid]), fminf(pmn[2][tid], pmn[3][tid]));
        float MX = fmaxf(fmaxf(pmx[0][tid], pmx[1][tid]), fmaxf(pmx[2][tid], pmx[3][tid]));
        atomicAdd(&g_st.sum[tid], S);
        atomicAdd(&g_st.sumsq[tid], Q);
        atomicMax(&g_st.mininv[tid], ~fmap(MN));
        atomicMax(&g_st.maxu[tid], fmap(MX));
    }
}

// ---------- kernel 2: per-l grid parameters ----------
__global__ void lparam_kernel(const float* __restrict__ gamma,
                              const float* __restrict__ bn_bias) {
    int l = threadIdx.x;
    if (l >= L_SZ) return;
    float mean = g_st.sum[l] * (1.f / (float)B_SZ);
    float var  = g_st.sumsq[l] * (1.f / (float)B_SZ) - mean * mean;
    float sc   = gamma[l] * rsqrtf(var + BN_EPS);
    float sh   = bn_bias[l] - mean * sc;
    float xmin = funmap(~g_st.mininv[l]);
    float xmax = funmap(g_st.maxu[l]);
    float a1 = fmaf(sc, xmin, sh), a2 = fmaf(sc, xmax, sh);
    float xnmin = fminf(a1, a2), xnmax = fmaxf(a1, a2);
    float range = xnmax - xnmin;
    float h     = range / (float)NCELL;
    float inv_h = (float)NCELL / range;
    g_lpXmin[l] = xnmin;
    g_lpH[l]    = h;
    g_lpA[l]    = sc * inv_h;
    g_lpC[l]    = (sh - xnmin) * inv_h;
}

// ---------- kernel 3: tabulate each net, layout [l][cell][k] ----------
__global__ void __launch_bounds__(128) build_kernel(
    const float* __restrict__ W1, const float* __restrict__ b1,
    const float* __restrict__ W2, const float* __restrict__ b2,
    const float* __restrict__ W3, const float* __restrict__ b3,
    const float* __restrict__ W4, const float* __restrict__ b4,
    const float* __restrict__ alpha)
{
    __shared__ __align__(16) u64 sw1[8], sb1[8], sw2[64], sb2[8], sw3[48], sb3[6], sw4[6];
    __shared__ u64 sb4;
    __shared__ float nodes[NCELL + 2];

    const int l = blockIdx.x, k = blockIdx.y, tid = threadIdx.x;
    const int nb = k * L_SZ + l;

    if (tid < 8)  sw1[tid] = dup2(W1[nb * 8 + tid]);
    if (tid < 8)  sb1[tid] = dup2(b1[nb * 8 + tid]);
    if (tid < 64) sw2[tid] = dup2(W2[nb * 64 + tid]);
    if (tid < 8)  sb2[tid] = dup2(b2[nb * 8 + tid]);
    if (tid < 48) sw3[tid] = dup2(W3[nb * 48 + tid]);
    if (tid < 6)  sb3[tid] = dup2(b3[nb * 6 + tid]);
    if (tid < 6)  sw4[tid] = dup2(W4[nb * 6 + tid]);
    if (tid == 0) sb4 = dup2(b4[nb]);
    __syncthreads();

    const float xnmin = g_lpXmin[l];
    const float h     = g_lpH[l];

    // evaluate node pairs (2i, 2i+1), packed f32x2
    for (int i = tid; i < NCELL / 2 + 1; i += 128) {
        float x0 = fmaf((float)(2 * i), h, xnmin);
        u64 xn = pack2(x0, x0 + h);

        u64 h1[8];
        #pragma unroll
        for (int j = 0; j < 8; ++j) h1[j] = relu2(ffma2(xn, sw1[j], sb1[j]));
        u64 h2[8];
        #pragma unroll
        for (int j = 0; j < 8; ++j) {
            u64 a = sb2[j];
            #pragma unroll
            for (int q = 0; q < 8; ++q) a = ffma2(h1[q], sw2[j * 8 + q], a);
            h2[j] = relu2(a);
        }
        u64 h3[6];
        #pragma unroll
        for (int j = 0; j < 6; ++j) {
            u64 a = sb3[j];
            #pragma unroll
            for (int q = 0; q < 8; ++q) a = ffma2(h2[q], sw3[j * 8 + q], a);
            h3[j] = relu2(a);
        }
        u64 f = sb4;
        #pragma unroll
        for (int j = 0; j < 6; ++j) f = ffma2(h3[j], sw4[j], f);

        float2 fv = unpack2(f);
        int n0 = 2 * i;
        if (n0 <= NCELL)     nodes[n0] = fv.x;
        if (n0 + 1 <= NCELL) nodes[n0 + 1] = fv.y;
    }
    __syncthreads();

    const float al = alpha[l * K_SZ + k];
    for (int i = tid; i < NCELL; i += 128) {
        float f0 = nodes[i], f1 = nodes[i + 1];
        g_table[(l * NCELL + i) * K_SZ + k] = make_float2(al * f0, al * (f1 - f0));
    }
}

// ---------- kernel 4: warp-per-sample eval, shuffle-broadcast indices ----------
__global__ void __launch_bounds__(128) eval_kernel(
    const float* __restrict__ x,
    const float* __restrict__ beta, float* __restrict__ out)
{
    const int tid  = threadIdx.x;
    const int lane = tid & 31;
    const int warp = tid >> 5;
    const int b    = blockIdx.x * 4 + warp;       // one sample per warp

    // lane l owns feature l: one coalesced 100B x-load per warp
    float u_own = 0.f;
    if (lane < L_SZ)
        u_own = fmaf(x[b * L_SZ + lane], g_lpA[lane], g_lpC[lane]);

    float acc0 = (lane < K_SZ) ? beta[lane] : 0.f;
    float acc1 = 0.f, acc2 = 0.f, acc3 = 0.f;

    #pragma unroll
    for (int l = 0; l < L_SZ; ++l) {
        float u = __shfl_sync(0xFFFFFFFFu, u_own, l);
        int idx = __float2int_rd(u);
        idx = min(max(idx, 0), NCELL - 1);
        float frac = u - (float)idx;
        if (lane < K_SZ) {
            float2 td = g_table[(l * NCELL + idx) * K_SZ + lane];  // 200B contiguous/warp
            float v = fmaf(frac, td.y, td.x);
            if ((l & 3) == 0) acc0 += v;
            else if ((l & 3) == 1) acc1 += v;
            else if ((l & 3) == 2) acc2 += v;
            else acc3 += v;
        }
    }

    if (lane < K_SZ) out[b * K_SZ + lane] = ((acc0 + acc1) + (acc2 + acc3));
}

extern "C" void kernel_launch(void* const* d_in, const int* in_sizes, int n_in,
                              void* d_out, int out_size) {
    const float* x      = (const float*)d_in[0];
    const float* gamma  = (const float*)d_in[1];
    const float* bnb    = (const float*)d_in[2];
    const float* W1     = (const float*)d_in[3];
    const float* b1     = (const float*)d_in[4];
    const float* W2     = (const float*)d_in[5];
    const float* b2     = (const float*)d_in[6];
    const float* W3     = (const float*)d_in[7];
    const float* b3     = (const float*)d_in[8];
    const float* W4     = (const float*)d_in[9];
    const float* b4     = (const float*)d_in[10];
    const float* alpha  = (const float*)d_in[11];
    const float* beta   = (const float*)d_in[12];
    float* out = (float*)d_out;

    void* p_st = nullptr;
    cudaGetSymbolAddress(&p_st, g_st);
    cudaMemsetAsync(p_st, 0, sizeof(Stats));   // zero = identity for all four reductions

    prologue_kernel<<<B_SZ / 64, 128>>>(x);
    lparam_kernel<<<1, 32>>>(gamma, bnb);
    build_kernel<<<dim3(L_SZ, K_SZ), 128>>>(W1, b1, W2, b2, W3, b3, W4, b4, alpha);
    eval_kernel<<<B_SZ / 4, 128>>>(x, beta, out);
}